// round 16
// baseline (speedup 1.0000x reference)
#include <cuda_runtime.h>
#include <cuda_fp16.h>
#include <cstdint>
#include <math.h>

#define T_ 1024
#define DIM_ 2048
#define NH_ 32

__device__ __align__(16) __half g_qf[T_ * DIM_];
__device__ __align__(16) __half g_xf[T_ * DIM_];
__device__ __align__(16) __half g_chf[T_ * 8 * DIM_];
__device__ __align__(16) __half g_wqf[DIM_ * DIM_];
__device__ __align__(16) __half g_wktf[DIM_ * DIM_];
__device__ __align__(16) __half g_wvf[DIM_ * DIM_];
__device__ __align__(16) __half g_wof[DIM_ * DIM_];
__device__ __align__(16) __half g_qkf[(size_t)NH_ * T_ * DIM_];
__device__ __align__(16) __half g_mxf[(size_t)NH_ * T_ * DIM_];
__device__ __align__(16) __half g_attf[T_ * DIM_];

__device__ __forceinline__ uint32_t smem_u32(const void* p) {
    uint32_t a;
    asm("{ .reg .u64 t; cvta.to.shared.u64 t, %1; cvt.u32.u64 %0, t; }" : "=r"(a) : "l"(p));
    return a;
}
__device__ __forceinline__ uint32_t swz64(uint32_t o) { return o ^ ((o >> 3) & 0x30); }
__device__ __forceinline__ uint32_t swzA(uint32_t o) { return o ^ ((o >> 3) & 0x70); }  // 128B rows
__device__ __forceinline__ uint32_t swzB(uint32_t o) { return o ^ ((o >> 5) & 0x70); }  // 512B rows
__device__ __forceinline__ void ldsm4(uint32_t& r0, uint32_t& r1, uint32_t& r2,
                                      uint32_t& r3, uint32_t a) {
    asm volatile("ldmatrix.sync.aligned.m8n8.x4.shared.b16 {%0,%1,%2,%3}, [%4];"
                 : "=r"(r0), "=r"(r1), "=r"(r2), "=r"(r3) : "r"(a));
}
__device__ __forceinline__ void ldsm4t(uint32_t& r0, uint32_t& r1, uint32_t& r2,
                                       uint32_t& r3, uint32_t a) {
    asm volatile("ldmatrix.sync.aligned.m8n8.x4.trans.shared.b16 {%0,%1,%2,%3}, [%4];"
                 : "=r"(r0), "=r"(r1), "=r"(r2), "=r"(r3) : "r"(a));
}
__device__ __forceinline__ void mmaf16(float* c, const uint32_t* a, const uint32_t* b) {
    asm volatile("mma.sync.aligned.m16n8k16.row.col.f32.f16.f16.f32 "
                 "{%0,%1,%2,%3}, {%4,%5,%6,%7}, {%8,%9}, {%0,%1,%2,%3};"
                 : "+f"(c[0]), "+f"(c[1]), "+f"(c[2]), "+f"(c[3])
                 : "r"(a[0]), "r"(a[1]), "r"(a[2]), "r"(a[3]), "r"(b[0]), "r"(b[1]));
}
__device__ __forceinline__ void cp16(uint32_t s, const void* g) {
    asm volatile("cp.async.cg.shared.global [%0], [%1], 16;" :: "r"(s), "l"(g) : "memory");
}
__device__ __forceinline__ void cp16z(uint32_t s, const void* g, int sz) {
    asm volatile("cp.async.cg.shared.global [%0], [%1], 16, %2;" :: "r"(s), "l"(g), "r"(sz) : "memory");
}
__device__ __forceinline__ void cp_commit() { asm volatile("cp.async.commit_group;" ::: "memory"); }
template <int N> __device__ __forceinline__ void cp_wait() {
    asm volatile("cp.async.wait_group %0;" :: "n"(N) : "memory");
}

// one fused conversion kernel: grid.y selects the job
__global__ void __launch_bounds__(256)
cvt_multi(const float4* s0, uint2* d0, int n0,
          const float4* s1, uint2* d1, int n1,
          const float4* s2, uint2* d2, int n2,
          const float4* s3, uint2* d3, int n3,
          const float4* s4, uint2* d4, int n4) {
    const float4* s; uint2* d; int n;
    switch (blockIdx.y) {
        case 0: s = s0; d = d0; n = n0; break;
        case 1: s = s1; d = d1; n = n1; break;
        case 2: s = s2; d = d2; n = n2; break;
        case 3: s = s3; d = d3; n = n3; break;
        default: s = s4; d = d4; n = n4; break;
    }
    for (int i = blockIdx.x * blockDim.x + threadIdx.x; i < n; i += gridDim.x * blockDim.x) {
        float4 f = s[i];
        __half2 a = __float22half2_rn(make_float2(f.x, f.y));
        __half2 b = __float22half2_rn(make_float2(f.z, f.w));
        d[i] = make_uint2(*(uint32_t*)&a, *(uint32_t*)&b);
    }
}

// wkT[d][n] = wk[n][d], fp16
__global__ void __launch_bounds__(256)
transpose_cvt(const float* __restrict__ src, __half* __restrict__ dst) {
    __shared__ float ts[32][33];
    const int bx = blockIdx.x * 32, by = blockIdx.y * 32;
    const int x = threadIdx.x & 31, y0 = threadIdx.x >> 5;
#pragma unroll
    for (int i = 0; i < 4; i++)
        ts[y0 + i * 8][x] = src[(size_t)(by + y0 + i * 8) * 2048 + bx + x];
    __syncthreads();
#pragma unroll
    for (int i = 0; i < 4; i++) {
        const int d = bx + y0 + i * 8;
        dst[(size_t)d * 2048 + by + x] = __float2half_rn(ts[x][y0 + i * 8]);
    }
}

// ---- fp16 GEMM 128x128: C = A*B^T. OUT16: fp16 out, else fp32 ----
#define S_A 0
#define S_B 8192
#define S_STG 16384
#define S_SMEM (4 * S_STG)

__device__ __forceinline__ void s_load(const __half* A, const __half* B,
                                       int bm, int bn, int kc, uint32_t stg, int tid) {
#pragma unroll
    for (int j = 0; j < 2; j++) {
        const int idx = j * 256 + tid, r = idx >> 2, c = idx & 3;
        const uint32_t so = swz64((uint32_t)(r * 64 + c * 16));
        cp16(stg + S_A + so, A + (size_t)(bm + r) * 2048 + kc + c * 8);
        cp16(stg + S_B + so, B + (size_t)(bn + r) * 2048 + kc + c * 8);
    }
}

template <int OUT16>
__global__ void __launch_bounds__(256, 1)
gemm_f16s(const __half* __restrict__ A, const __half* __restrict__ B,
          float* __restrict__ C, __half* __restrict__ Ch) {
    extern __shared__ char sm[];
    const uint32_t sb = smem_u32(sm);
    const int tid = threadIdx.x, lane = tid & 31, wid = tid >> 5;
    const int wm = wid >> 2, wn = wid & 3;
    const int bm = blockIdx.y * 128, bn = blockIdx.x * 128;

    float acc[4][4][4];
#pragma unroll
    for (int i = 0; i < 4; i++)
#pragma unroll
        for (int j = 0; j < 4; j++)
#pragma unroll
            for (int r = 0; r < 4; r++) acc[i][j][r] = 0.f;

    s_load(A, B, bm, bn, 0, sb, tid); cp_commit();
    s_load(A, B, bm, bn, 32, sb + S_STG, tid); cp_commit();
    s_load(A, B, bm, bn, 64, sb + 2 * S_STG, tid); cp_commit();
    const int lr = (lane & 7) + ((lane >> 3) & 1) * 8, lc16 = lane >> 4;

    for (int c = 0; c < 64; c++) {
        cp_wait<2>();
        __syncthreads();
        if (c + 3 < 64)
            s_load(A, B, bm, bn, (c + 3) * 32, sb + (uint32_t)((c + 3) & 3) * S_STG, tid);
        cp_commit();
        const uint32_t stg = sb + (uint32_t)(c & 3) * S_STG;
#pragma unroll
        for (int ks = 0; ks < 2; ks++) {
            uint32_t a[4][4];
#pragma unroll
            for (int mi = 0; mi < 4; mi++) {
                const int r = wm * 64 + mi * 16 + lr;
                const uint32_t so = swz64((uint32_t)(r * 64 + (ks * 2 + lc16) * 16));
                ldsm4(a[mi][0], a[mi][1], a[mi][2], a[mi][3], stg + S_A + so);
            }
#pragma unroll
            for (int nj = 0; nj < 2; nj++) {
                const int r = wn * 32 + nj * 16 + lr;
                const uint32_t so = swz64((uint32_t)(r * 64 + (ks * 2 + lc16) * 16));
                uint32_t h0, h1, h2, h3;
                ldsm4(h0, h1, h2, h3, stg + S_B + so);
                uint32_t b0[2] = {h0, h2}, b1[2] = {h1, h3};
#pragma unroll
                for (int mi = 0; mi < 4; mi++) {
                    mmaf16(acc[mi][nj * 2], a[mi], b0);
                    mmaf16(acc[mi][nj * 2 + 1], a[mi], b1);
                }
            }
        }
    }
    const int gr = lane >> 2, gc = (lane & 3) << 1;
#pragma unroll
    for (int mi = 0; mi < 4; mi++)
#pragma unroll
        for (int nn = 0; nn < 4; nn++) {
            const int row = bm + wm * 64 + mi * 16 + gr;
            const int col = bn + wn * 32 + nn * 8 + gc;
            if (OUT16) {
                __half2 p0 = __float22half2_rn(make_float2(acc[mi][nn][0], acc[mi][nn][1]));
                __half2 p1 = __float22half2_rn(make_float2(acc[mi][nn][2], acc[mi][nn][3]));
                *(uint32_t*)(Ch + (size_t)row * 2048 + col) = *(uint32_t*)&p0;
                *(uint32_t*)(Ch + (size_t)(row + 8) * 2048 + col) = *(uint32_t*)&p1;
            } else {
                *(float2*)(C + (size_t)row * 2048 + col) = make_float2(acc[mi][nn][0], acc[mi][nn][1]);
                *(float2*)(C + (size_t)(row + 8) * 2048 + col) = make_float2(acc[mi][nn][2], acc[mi][nn][3]);
            }
        }
}

// ---- qk GEMM v3: persistent-B loop. CTA fixes (bn, z), holds wkT tile in
// smem, loops bm over all 16 blocks of 64 q-rows with double-buffered A.
// qk[t][z][d] = q[t, z*64:+64] @ wkT[d, z*64:+64]^T (K=64)
__global__ void __launch_bounds__(256)
gemm_qk(const __half* __restrict__ qf, const __half* __restrict__ wkT,
        __half* __restrict__ qk) {
    __shared__ __align__(16) char sm[32768];   // B 16K + A 2x8K
    const uint32_t sb = smem_u32(sm);
    const int tid = threadIdx.x, lane = tid & 31, wid = tid >> 5;
    const int wm = wid >> 2, wn = wid & 3;     // warp tile 32x32
    const int bn = blockIdx.x * 128, z = blockIdx.y;
    const int lr = (lane & 7) + ((lane >> 3) & 1) * 8, lc16 = lane >> 4;

    // group 0: B (persistent) + A(bm=0)
#pragma unroll
    for (int it = 0; it < 4; it++) {
        const int idx = it * 256 + tid, r = idx >> 3, c = idx & 7;
        cp16(sb + swzA((uint32_t)(r * 128 + c * 16)),
             wkT + (size_t)(bn + r) * 2048 + z * 64 + c * 8);
    }
#pragma unroll
    for (int it = 0; it < 2; it++) {
        const int idx = it * 256 + tid, r = idx >> 3, c = idx & 7;
        cp16(sb + 16384 + swzA((uint32_t)(r * 128 + c * 16)),
             qf + (size_t)r * 2048 + z * 64 + c * 8);
    }
    cp_commit();
    // group 1: A(bm=1)
#pragma unroll
    for (int it = 0; it < 2; it++) {
        const int idx = it * 256 + tid, r = idx >> 3, c = idx & 7;
        cp16(sb + 24576 + swzA((uint32_t)(r * 128 + c * 16)),
             qf + (size_t)(64 + r) * 2048 + z * 64 + c * 8);
    }
    cp_commit();

    // B fragments loaded once after group 0 lands (first loop iter waits)
    uint32_t bf[4][2][2];    // [kg][nj][2]
    bool bloaded = false;

    for (int bm = 0; bm < 16; bm++) {
        cp_wait<1>();
        __syncthreads();
        if (!bloaded) {
            bloaded = true;
#pragma unroll
            for (int kg = 0; kg < 4; kg++)
#pragma unroll
                for (int nj = 0; nj < 2; nj++) {
                    const uint32_t so = swzA(
                        (uint32_t)((wn * 32 + nj * 16 + lr) * 128 + kg * 32 + lc16 * 16));
                    uint32_t h0, h1, h2, h3;
                    ldsm4(h0, h1, h2, h3, sb + so);
                    bf[kg][nj][0] = (lr < 8 || true) ? h0 : h0;  // keep simple
                    bf[kg][nj][0] = h0; bf[kg][nj][1] = h2;
                    // second n8 half uses h1,h3; store interleaved below
                    // (we keep full 4 regs per (kg,nj) in two calls)
                    // workaround: store h1,h3 in a parallel array
                    // -> use combined layout instead:
                    (void)h1; (void)h3;
                }
            // reload properly with full fragments (b0 and b1 both needed)
        }
        const uint32_t astg = sb + 16384 + (uint32_t)(bm & 1) * 8192;

        float acc[2][4][4];
#pragma unroll
        for (int i = 0; i < 2; i++)
#pragma unroll
            for (int j = 0; j < 4; j++)
#pragma unroll
                for (int r = 0; r < 4; r++) acc[i][j][r] = 0.f;

#pragma unroll
        for (int kg = 0; kg < 4; kg++) {
            uint32_t a[2][4];
#pragma unroll
            for (int mi = 0; mi < 2; mi++) {
                const uint32_t so =
                    swzA((uint32_t)((mi * 32 + wm * 0 + wm * 32 + lr - wm * 32 + wm * 32) * 0));
                (void)so;
                const uint32_t soA = swzA(
                    (uint32_t)((wm * 32 + mi * 16 + lr) * 128 + kg * 32 + lc16 * 16));
                ldsm4(a[mi][0], a[mi][1], a[mi][2], a[mi][3], astg + soA);
            }
#pragma unroll
            for (int nj = 0; nj < 2; nj++) {
                const uint32_t soB = swzA(
                    (uint32_t)((wn * 32 + nj * 16 + lr) * 128 + kg * 32 + lc16 * 16));
                uint32_t h0, h1, h2, h3;
                ldsm4(h0, h1, h2, h3, sb + soB);
                uint32_t b0[2] = {h0, h2}, b1[2] = {h1, h3};
#pragma unroll
                for (int mi = 0; mi < 2; mi++) {
                    mmaf16(acc[mi][nj * 2], a[mi], b0);
                    mmaf16(acc[mi][nj * 2 + 1], a[mi], b1);
                }
            }
        }

        const int gr = lane >> 2, gc = (lane & 3) << 1;
#pragma unroll
        for (int mi = 0; mi < 2; mi++)
#pragma unroll
            for (int nn = 0; nn < 4; nn++) {
                const int row = bm * 64 + wm * 32 + mi * 16 + gr;
                const int col = bn + wn * 32 + nn * 8 + gc;
                __half2 p0 = __float22half2_rn(make_float2(acc[mi][nn][0], acc[mi][nn][1]));
                __half2 p1 = __float22half2_rn(make_float2(acc[mi][nn][2], acc[mi][nn][3]));
                *(uint32_t*)(qk + ((size_t)row * 32 + z) * 2048 + col) = *(uint32_t*)&p0;
                *(uint32_t*)(qk + ((size_t)(row + 8) * 32 + z) * 2048 + col) = *(uint32_t*)&p1;
            }
        __syncthreads();
        if (bm + 2 < 16) {
            const uint32_t dst = sb + 16384 + (uint32_t)(bm & 1) * 8192;
#pragma unroll
            for (int it = 0; it < 2; it++) {
                const int idx = it * 256 + tid, r = idx >> 3, c = idx & 7;
                cp16(dst + swzA((uint32_t)(r * 128 + c * 16)),
                     qf + (size_t)((bm + 2) * 64 + r) * 2048 + z * 64 + c * 8);
            }
        }
        cp_commit();
    }
}

// ---- batched N=64 fp16 GEMM: att = mixed[z] @ wv_z^T ----
#define N64_A 0
#define N64_B 8192
#define N64_STG 12288
#define N64_SMEM (4 * N64_STG)

__device__ __forceinline__ void n64_load(const __half* A, const __half* B,
                                         int bm, int kc, uint32_t stg, int tid) {
#pragma unroll
    for (int j = 0; j < 2; j++) {
        const int idx = j * 256 + tid, r = idx >> 2, c = idx & 3;
        cp16(stg + N64_A + swz64((uint32_t)(r * 64 + c * 16)),
             A + (size_t)(bm + r) * 2048 + kc + c * 8);
    }
    {
        const int r = tid >> 2, c = tid & 3;
        if (r < 64)
            cp16(stg + N64_B + swz64((uint32_t)(r * 64 + c * 16)),
                 B + (size_t)r * 2048 + kc + c * 8);
    }
}

__global__ void __launch_bounds__(256, 1)
gemm_n64(const __half* __restrict__ A0, const __half* __restrict__ B0,
         __half* __restrict__ Co) {
    extern __shared__ char sm[];
    const uint32_t sb = smem_u32(sm);
    const int tid = threadIdx.x, lane = tid & 31, wid = tid >> 5;
    const int wm = wid >> 1, wn = wid & 1;
    const int bm = blockIdx.x * 128, z = blockIdx.y;
    const __half* A = A0 + (size_t)z * T_ * 2048;
    const __half* B = B0 + (size_t)z * 64 * 2048;

    float acc[2][4][4];
#pragma unroll
    for (int i = 0; i < 2; i++)
#pragma unroll
        for (int j = 0; j < 4; j++)
#pragma unroll
            for (int r = 0; r < 4; r++) acc[i][j][r] = 0.f;

    n64_load(A, B, bm, 0, sb, tid); cp_commit();
    n64_load(A, B, bm, 32, sb + N64_STG, tid); cp_commit();
    n64_load(A, B, bm, 64, sb + 2 * N64_STG, tid); cp_commit();
    const int lr = (lane & 7) + ((lane >> 3) & 1) * 8, lc16 = lane >> 4;

    for (int c = 0; c < 64; c++) {
        cp_wait<2>();
        __syncthreads();
        if (c + 3 < 64)
            n64_load(A, B, bm, (c + 3) * 32, sb + (uint32_t)((c + 3) & 3) * N64_STG, tid);
        cp_commit();
        const uint32_t stg = sb + (uint32_t)(c & 3) * N64_STG;
#pragma unroll
        for (int ks = 0; ks < 2; ks++) {
            uint32_t a[2][4];
#pragma unroll
            for (int mi = 0; mi < 2; mi++) {
                const int r = wm * 32 + mi * 16 + lr;
                const uint32_t so = swz64((uint32_t)(r * 64 + (ks * 2 + lc16) * 16));
                ldsm4(a[mi][0], a[mi][1], a[mi][2], a[mi][3], stg + N64_A + so);
            }
#pragma unroll
            for (int nj = 0; nj < 2; nj++) {
                const int r = wn * 32 + nj * 16 + lr;
                const uint32_t so = swz64((uint32_t)(r * 64 + (ks * 2 + lc16) * 16));
                uint32_t h0, h1, h2, h3;
                ldsm4(h0, h1, h2, h3, stg + N64_B + so);
                uint32_t b0[2] = {h0, h2}, b1[2] = {h1, h3};
#pragma unroll
                for (int mi = 0; mi < 2; mi++) {
                    mmaf16(acc[mi][nj * 2], a[mi], b0);
                    mmaf16(acc[mi][nj * 2 + 1], a[mi], b1);
                }
            }
        }
    }
    const int gr = lane >> 2, gc = (lane & 3) << 1;
#pragma unroll
    for (int mi = 0; mi < 2; mi++)
#pragma unroll
        for (int nn = 0; nn < 4; nn++) {
            const int row = bm + wm * 32 + mi * 16 + gr;
            const int col = wn * 32 + nn * 8 + gc;
            const size_t i0 = (size_t)row * 2048 + z * 64 + col;
            const size_t i1 = i0 + (size_t)8 * 2048;
            __half2 p0 = __float22half2_rn(make_float2(acc[mi][nn][0], acc[mi][nn][1]));
            __half2 p1 = __float22half2_rn(make_float2(acc[mi][nn][2], acc[mi][nn][3]));
            *(uint32_t*)(Co + i0) = *(uint32_t*)&p0;
            *(uint32_t*)(Co + i1) = *(uint32_t*)&p1;
        }
}

// ---- attnmix3: tensor-core scores + softmax + tensor-core mix ----
#define MX_QK 0
#define MX_CH 32768
#define MX_SC 98304
#define MX_ATH 106752
#define MX_SMEM 110848
#define SCP 66

__device__ __forceinline__ void ch_load(const __half* chf, int t, int nc,
                                        uint32_t cstg, int tid) {
    const int base = (t - 7) * 8;
#pragma unroll
    for (int it = 0; it < 8; it++) {
        const int idx = it * 256 + tid;
        const int j = idx >> 5, ch = idx & 31;
        const int p = base + j;
        cp16z(cstg + swzB((uint32_t)(j * 512 + ch * 16)),
              chf + (size_t)(p < 0 ? 0 : p) * 2048 + nc * 256 + ch * 8, p >= 0 ? 16 : 0);
    }
}
__device__ __forceinline__ void qk_load(const __half* qk, int t, int nc,
                                        uint32_t qstg, int tid) {
#pragma unroll
    for (int it = 0; it < 4; it++) {
        const int idx = it * 256 + tid;
        const int r = idx >> 5, ch = idx & 31;
        cp16(qstg + swzB((uint32_t)(r * 512 + ch * 16)),
             qk + ((size_t)t * 32 + r) * 2048 + nc * 256 + ch * 8);
    }
}

__global__ void __launch_bounds__(256, 1)
attnmix3(const __half* __restrict__ qk, const __half* __restrict__ chf,
         __half* __restrict__ mx) {
    extern __shared__ char sm[];
    const uint32_t sb = smem_u32(sm);
    float* sc = (float*)(sm + MX_SC);
    const int t = blockIdx.x, tid = threadIdx.x;
    const int lane = tid & 31, wid = tid >> 5;
    const int lr = (lane & 7) + ((lane >> 3) & 1) * 8, lc16 = lane >> 4;

    qk_load(qk, t, 0, sb + MX_QK, tid);
    ch_load(chf, t, 0, sb + MX_CH, tid);
    cp_commit();
    qk_load(qk, t, 1, sb + MX_QK + 16384, tid);
    ch_load(chf, t, 1, sb + MX_CH + 32768, tid);
    cp_commit();

    const int smi = wid >> 2, snj = wid & 3;
    float sa0[4] = {0, 0, 0, 0}, sa1[4] = {0, 0, 0, 0};
    for (int nc = 0; nc < 8; nc++) {
        cp_wait<1>();
        __syncthreads();
        const uint32_t qstg = sb + MX_QK + (uint32_t)(nc & 1) * 16384;
        const uint32_t cstg = sb + MX_CH + (uint32_t)(nc & 1) * 32768;
#pragma unroll
        for (int kg = 0; kg < 16; kg++) {
            uint32_t a[4];
            ldsm4(a[0], a[1], a[2], a[3],
                  qstg + swzB((uint32_t)((smi * 16 + lr) * 512 + kg * 32 + lc16 * 16)));
            uint32_t h0, h1, h2, h3;
            ldsm4(h0, h1, h2, h3,
                  cstg + swzB((uint32_t)((snj * 16 + lr) * 512 + kg * 32 + lc16 * 16)));
            uint32_t b0[2] = {h0, h2}, b1[2] = {h1, h3};
            mmaf16(sa0, a, b0);
            mmaf16(sa1, a, b1);
        }
        __syncthreads();
        if (nc + 2 < 8) {
            qk_load(qk, t, nc + 2, sb + MX_QK + (uint32_t)(nc & 1) * 16384, tid);
            ch_load(chf, t, nc + 2, sb + MX_CH + (uint32_t)(nc & 1) * 32768, tid);
        }
        cp_commit();
    }
    {
        const int gr = lane >> 2, gc = (lane & 3) << 1;
        const int r0 = smi * 16 + gr, c0 = snj * 16 + gc;
        sc[r0 * SCP + c0] = sa0[0] * 0.125f;
        sc[r0 * SCP + c0 + 1] = sa0[1] * 0.125f;
        sc[(r0 + 8) * SCP + c0] = sa0[2] * 0.125f;
        sc[(r0 + 8) * SCP + c0 + 1] = sa0[3] * 0.125f;
        sc[r0 * SCP + c0 + 8] = sa1[0] * 0.125f;
        sc[r0 * SCP + c0 + 9] = sa1[1] * 0.125f;
        sc[(r0 + 8) * SCP + c0 + 8] = sa1[2] * 0.125f;
        sc[(r0 + 8) * SCP + c0 + 9] = sa1[3] * 0.125f;
    }
    __syncthreads();

    {
        const int r = tid >> 3, l8 = tid & 7;
        float vals[8], m = -1e30f;
#pragma unroll
        for (int i = 0; i < 8; i++) { vals[i] = sc[r * SCP + l8 + i * 8]; m = fmaxf(m, vals[i]); }
#pragma unroll
        for (int o = 4; o; o >>= 1) m = fmaxf(m, __shfl_xor_sync(0xffffffffu, m, o));
        float s = 0.f;
#pragma unroll
        for (int i = 0; i < 8; i++) { vals[i] = expf(vals[i] - m); s += vals[i]; }
#pragma unroll
        for (int o = 4; o; o >>= 1) s += __shfl_xor_sync(0xffffffffu, s, o);
        const float inv = 1.f / s;
#pragma unroll
        for (int i = 0; i < 8; i++) {
            const uint32_t o = (uint32_t)(r * 128 + l8 * 2 + i * 16);
            *(__half*)(sm + MX_ATH + swzA(o)) = __float2half_rn(vals[i] * inv);
        }
    }
    __syncthreads();

    uint32_t aH[2][4][4];
#pragma unroll
    for (int mi = 0; mi < 2; mi++)
#pragma unroll
        for (int kg = 0; kg < 4; kg++) {
            const uint32_t o = (uint32_t)((mi * 16 + (lane & 15)) * 128 + kg * 32 + (lane >> 4) * 16);
            ldsm4(aH[mi][kg][0], aH[mi][kg][1], aH[mi][kg][2], aH[mi][kg][3],
                  sb + MX_ATH + swzA(o));
        }

    const int nb = wid * 32;
    for (int i = 0; i < 8; i++) {
        const int nc = (6 + i) & 7;
        if (i >= 2) cp_wait<1>();
        __syncthreads();
        const uint32_t stg = sb + MX_CH + (uint32_t)(nc & 1) * 32768;

        float acc[2][4][4];
#pragma unroll
        for (int ii = 0; ii < 2; ii++)
#pragma unroll
            for (int j = 0; j < 4; j++)
#pragma unroll
                for (int r = 0; r < 4; r++) acc[ii][j][r] = 0.f;

#pragma unroll
        for (int g = 0; g < 2; g++) {
#pragma unroll
            for (int kg = 0; kg < 4; kg++) {
                const uint32_t o = (uint32_t)((kg * 16 + (lane & 15)) * 512 +
                                              nb * 2 + g * 32 + (lane >> 4) * 16);
                uint32_t h0, h1, h2, h3;
                ldsm4t(h0, h1, h2, h3, stg + swzB(o));
                uint32_t b0[2] = {h0, h1}, b1[2] = {h2, h3};
#pragma unroll
                for (int mi = 0; mi < 2; mi++) {
                    mmaf16(acc[mi][g * 2], aH[mi][kg], b0);
                    mmaf16(acc[mi][g * 2 + 1], aH[mi][kg], b1);
                }
            }
        }
        const int gr = lane >> 2, gc = (lane & 3) << 1;
#pragma unroll
        for (int mi = 0; mi < 2; mi++)
#pragma unroll
            for (int nj = 0; nj < 4; nj++) {
                const int h = mi * 16 + gr;
                const int col = nc * 256 + nb + nj * 8 + gc;
                const size_t i0 = ((size_t)h * T_ + t) * 2048 + col;
                const size_t i1 = ((size_t)(h + 8) * T_ + t) * 2048 + col;
                __half2 p0 = __float22half2_rn(make_float2(acc[mi][nj][0], acc[mi][nj][1]));
                __half2 p1 = __float22half2_rn(make_float2(acc[mi][nj][2], acc[mi][nj][3]));
                *(uint32_t*)(mx + i0) = *(uint32_t*)&p0;
                *(uint32_t*)(mx + i1) = *(uint32_t*)&p1;
            }
        __syncthreads();
        if (i + 2 < 8) ch_load(chf, t, (6 + i + 2) & 7, stg, tid);
        cp_commit();
    }
}

extern "C" void kernel_launch(void* const* d_in, const int* in_sizes, int n_in,
                              void* d_out, int out_size) {
    const float* x = (const float*)d_in[0];
    const float* chars = (const float*)d_in[1];
    const float* wq = (const float*)d_in[2];
    const float* wk = (const float*)d_in[3];
    const float* wv = (const float*)d_in[4];
    const float* wo = (const float*)d_in[5];
    float* out = (float*)d_out;

    __half *qf, *xf, *chf, *wqf, *wktf, *wvf, *wof, *qkf, *mxf, *attf;
    cudaGetSymbolAddress((void**)&qf, g_qf);     cudaGetSymbolAddress((void**)&xf, g_xf);
    cudaGetSymbolAddress((void**)&chf, g_chf);   cudaGetSymbolAddress((void**)&wqf, g_wqf);
    cudaGetSymbolAddress((void**)&wktf, g_wktf); cudaGetSymbolAddress((void**)&wvf, g_wvf);
    cudaGetSymbolAddress((void**)&wof, g_wof);   cudaGetSymbolAddress((void**)&qkf, g_qkf);
    cudaGetSymbolAddress((void**)&mxf, g_mxf);   cudaGetSymbolAddress((void**)&attf, g_attf);

    cudaFuncSetAttribute(gemm_f16s<0>, cudaFuncAttributeMaxDynamicSharedMemorySize, S_SMEM);
    cudaFuncSetAttribute(gemm_f16s<1>, cudaFuncAttributeMaxDynamicSharedMemorySize, S_SMEM);
    cudaFuncSetAttribute(gemm_n64, cudaFuncAttributeMaxDynamicSharedMemorySize, N64_SMEM);
    cudaFuncSetAttribute(attnmix3, cudaFuncAttributeMaxDynamicSharedMemorySize, MX_SMEM);

    cvt_multi<<<dim3(2048, 5), 256>>>(
        (const float4*)x,     (uint2*)xf,  T_ * DIM_ / 4,
        (const float4*)chars, (uint2*)chf, T_ * 8 * DIM_ / 4,
        (const float4*)wq,    (uint2*)wqf, DIM_ * DIM_ / 4,
        (const float4*)wv,    (uint2*)wvf, DIM_ * DIM_ / 4,
        (const float4*)wo,    (uint2*)wof, DIM_ * DIM_ / 4);
    transpose_cvt<<<dim3(64, 64), 256>>>(wk, wktf);

    gemm_f16s<1><<<dim3(16, 8), 256, S_SMEM>>>(xf, wqf, nullptr, qf);   // q (fp16)
    gemm_qk<<<dim3(16, 32), 256>>>(qf, wktf, qkf);                      // qk (persistent-B)
    attnmix3<<<T_, 256, MX_SMEM>>>(qkf, chf, mxf);                      // scores+softmax+mix
    gemm_n64<<<dim3(8, 32), 256, N64_SMEM>>>(mxf, wvf, attf);           // v proj
    gemm_f16s<0><<<dim3(16, 8), 256, S_SMEM>>>(attf, wof, out, nullptr); // o proj
}

// round 17
// speedup vs baseline: 1.0343x; 1.0343x over previous
#include <cuda_runtime.h>
#include <cuda_fp16.h>
#include <cstdint>
#include <math.h>

#define T_ 1024
#define DIM_ 2048
#define NH_ 32

__device__ __align__(16) __half g_qf[T_ * DIM_];
__device__ __align__(16) __half g_xf[T_ * DIM_];
__device__ __align__(16) __half g_chf[T_ * 8 * DIM_];
__device__ __align__(16) __half g_wqf[DIM_ * DIM_];
__device__ __align__(16) __half g_wktf[DIM_ * DIM_];
__device__ __align__(16) __half g_wvf[DIM_ * DIM_];
__device__ __align__(16) __half g_wof[DIM_ * DIM_];
__device__ __align__(16) __half g_qkf[(size_t)NH_ * T_ * DIM_];
__device__ __align__(16) __half g_mxf[(size_t)NH_ * T_ * DIM_];
__device__ __align__(16) __half g_attf[T_ * DIM_];

__device__ __forceinline__ uint32_t smem_u32(const void* p) {
    uint32_t a;
    asm("{ .reg .u64 t; cvta.to.shared.u64 t, %1; cvt.u32.u64 %0, t; }" : "=r"(a) : "l"(p));
    return a;
}
__device__ __forceinline__ uint32_t swz64(uint32_t o) { return o ^ ((o >> 3) & 0x30); }
__device__ __forceinline__ uint32_t swzA(uint32_t o) { return o ^ ((o >> 3) & 0x70); }  // 128B rows
__device__ __forceinline__ uint32_t swzB(uint32_t o) { return o ^ ((o >> 5) & 0x70); }  // 512B rows
__device__ __forceinline__ void ldsm4(uint32_t& r0, uint32_t& r1, uint32_t& r2,
                                      uint32_t& r3, uint32_t a) {
    asm volatile("ldmatrix.sync.aligned.m8n8.x4.shared.b16 {%0,%1,%2,%3}, [%4];"
                 : "=r"(r0), "=r"(r1), "=r"(r2), "=r"(r3) : "r"(a));
}
__device__ __forceinline__ void ldsm4t(uint32_t& r0, uint32_t& r1, uint32_t& r2,
                                       uint32_t& r3, uint32_t a) {
    asm volatile("ldmatrix.sync.aligned.m8n8.x4.trans.shared.b16 {%0,%1,%2,%3}, [%4];"
                 : "=r"(r0), "=r"(r1), "=r"(r2), "=r"(r3) : "r"(a));
}
__device__ __forceinline__ void mmaf16(float* c, const uint32_t* a, const uint32_t* b) {
    asm volatile("mma.sync.aligned.m16n8k16.row.col.f32.f16.f16.f32 "
                 "{%0,%1,%2,%3}, {%4,%5,%6,%7}, {%8,%9}, {%0,%1,%2,%3};"
                 : "+f"(c[0]), "+f"(c[1]), "+f"(c[2]), "+f"(c[3])
                 : "r"(a[0]), "r"(a[1]), "r"(a[2]), "r"(a[3]), "r"(b[0]), "r"(b[1]));
}
__device__ __forceinline__ void cp16(uint32_t s, const void* g) {
    asm volatile("cp.async.cg.shared.global [%0], [%1], 16;" :: "r"(s), "l"(g) : "memory");
}
__device__ __forceinline__ void cp16z(uint32_t s, const void* g, int sz) {
    asm volatile("cp.async.cg.shared.global [%0], [%1], 16, %2;" :: "r"(s), "l"(g), "r"(sz) : "memory");
}
__device__ __forceinline__ void cp_commit() { asm volatile("cp.async.commit_group;" ::: "memory"); }
template <int N> __device__ __forceinline__ void cp_wait() {
    asm volatile("cp.async.wait_group %0;" :: "n"(N) : "memory");
}

// fused conversion kernel: grid.y 0..4 = fp32->fp16 copies; 5 = wk transpose
__global__ void __launch_bounds__(256)
cvt_multi(const float4* s0, uint2* d0, int n0,
          const float4* s1, uint2* d1, int n1,
          const float4* s2, uint2* d2, int n2,
          const float4* s3, uint2* d3, int n3,
          const float4* s4, uint2* d4, int n4,
          const float* wk, __half* wkT) {
    if (blockIdx.y == 5) {
        // wkT[d][n] = wk[n][d]; 4096 32x32 tiles; 2 tiles per block
        __shared__ float ts[32][33];
        const int x = threadIdx.x & 31, y0 = threadIdx.x >> 5;
#pragma unroll
        for (int tile = 0; tile < 2; tile++) {
            const int tix = (blockIdx.x * 2 + tile);
            const int bx = (tix & 63) * 32, by = (tix >> 6) * 32;
#pragma unroll
            for (int i = 0; i < 4; i++)
                ts[y0 + i * 8][x] = wk[(size_t)(by + y0 + i * 8) * 2048 + bx + x];
            __syncthreads();
#pragma unroll
            for (int i = 0; i < 4; i++) {
                const int d = bx + y0 + i * 8;
                wkT[(size_t)d * 2048 + by + x] = __float2half_rn(ts[x][y0 + i * 8]);
            }
            __syncthreads();
        }
        return;
    }
    const float4* s; uint2* d; int n;
    switch (blockIdx.y) {
        case 0: s = s0; d = d0; n = n0; break;
        case 1: s = s1; d = d1; n = n1; break;
        case 2: s = s2; d = d2; n = n2; break;
        case 3: s = s3; d = d3; n = n3; break;
        default: s = s4; d = d4; n = n4; break;
    }
    for (int i = blockIdx.x * blockDim.x + threadIdx.x; i < n; i += gridDim.x * blockDim.x) {
        float4 f = s[i];
        __half2 a = __float22half2_rn(make_float2(f.x, f.y));
        __half2 b = __float22half2_rn(make_float2(f.z, f.w));
        d[i] = make_uint2(*(uint32_t*)&a, *(uint32_t*)&b);
    }
}

// ---- fp16 GEMM 128x128: C = A*B^T. OUT16: fp16 out, else fp32 ----
#define S_A 0
#define S_B 8192
#define S_STG 16384
#define S_SMEM (4 * S_STG)

__device__ __forceinline__ void s_load(const __half* A, const __half* B,
                                       int bm, int bn, int kc, uint32_t stg, int tid) {
#pragma unroll
    for (int j = 0; j < 2; j++) {
        const int idx = j * 256 + tid, r = idx >> 2, c = idx & 3;
        const uint32_t so = swz64((uint32_t)(r * 64 + c * 16));
        cp16(stg + S_A + so, A + (size_t)(bm + r) * 2048 + kc + c * 8);
        cp16(stg + S_B + so, B + (size_t)(bn + r) * 2048 + kc + c * 8);
    }
}

template <int OUT16>
__global__ void __launch_bounds__(256, 1)
gemm_f16s(const __half* __restrict__ A, const __half* __restrict__ B,
          float* __restrict__ C, __half* __restrict__ Ch) {
    extern __shared__ char sm[];
    const uint32_t sb = smem_u32(sm);
    const int tid = threadIdx.x, lane = tid & 31, wid = tid >> 5;
    const int wm = wid >> 2, wn = wid & 3;
    const int bm = blockIdx.y * 128, bn = blockIdx.x * 128;

    float acc[4][4][4];
#pragma unroll
    for (int i = 0; i < 4; i++)
#pragma unroll
        for (int j = 0; j < 4; j++)
#pragma unroll
            for (int r = 0; r < 4; r++) acc[i][j][r] = 0.f;

    s_load(A, B, bm, bn, 0, sb, tid); cp_commit();
    s_load(A, B, bm, bn, 32, sb + S_STG, tid); cp_commit();
    s_load(A, B, bm, bn, 64, sb + 2 * S_STG, tid); cp_commit();
    const int lr = (lane & 7) + ((lane >> 3) & 1) * 8, lc16 = lane >> 4;

    for (int c = 0; c < 64; c++) {
        cp_wait<2>();
        __syncthreads();
        if (c + 3 < 64)
            s_load(A, B, bm, bn, (c + 3) * 32, sb + (uint32_t)((c + 3) & 3) * S_STG, tid);
        cp_commit();
        const uint32_t stg = sb + (uint32_t)(c & 3) * S_STG;
#pragma unroll
        for (int ks = 0; ks < 2; ks++) {
            uint32_t a[4][4];
#pragma unroll
            for (int mi = 0; mi < 4; mi++) {
                const int r = wm * 64 + mi * 16 + lr;
                const uint32_t so = swz64((uint32_t)(r * 64 + (ks * 2 + lc16) * 16));
                ldsm4(a[mi][0], a[mi][1], a[mi][2], a[mi][3], stg + S_A + so);
            }
#pragma unroll
            for (int nj = 0; nj < 2; nj++) {
                const int r = wn * 32 + nj * 16 + lr;
                const uint32_t so = swz64((uint32_t)(r * 64 + (ks * 2 + lc16) * 16));
                uint32_t h0, h1, h2, h3;
                ldsm4(h0, h1, h2, h3, stg + S_B + so);
                uint32_t b0[2] = {h0, h2}, b1[2] = {h1, h3};
#pragma unroll
                for (int mi = 0; mi < 4; mi++) {
                    mmaf16(acc[mi][nj * 2], a[mi], b0);
                    mmaf16(acc[mi][nj * 2 + 1], a[mi], b1);
                }
            }
        }
    }
    const int gr = lane >> 2, gc = (lane & 3) << 1;
#pragma unroll
    for (int mi = 0; mi < 4; mi++)
#pragma unroll
        for (int nn = 0; nn < 4; nn++) {
            const int row = bm + wm * 64 + mi * 16 + gr;
            const int col = bn + wn * 32 + nn * 8 + gc;
            if (OUT16) {
                __half2 p0 = __float22half2_rn(make_float2(acc[mi][nn][0], acc[mi][nn][1]));
                __half2 p1 = __float22half2_rn(make_float2(acc[mi][nn][2], acc[mi][nn][3]));
                *(uint32_t*)(Ch + (size_t)row * 2048 + col) = *(uint32_t*)&p0;
                *(uint32_t*)(Ch + (size_t)(row + 8) * 2048 + col) = *(uint32_t*)&p1;
            } else {
                *(float2*)(C + (size_t)row * 2048 + col) = make_float2(acc[mi][nn][0], acc[mi][nn][1]);
                *(float2*)(C + (size_t)(row + 8) * 2048 + col) = make_float2(acc[mi][nn][2], acc[mi][nn][3]);
            }
        }
}

// ---- qk GEMM (R15 proven): qk[t][z][d] = q[t,z*64:+64] @ wkT[d,z*64:+64]^T ----
// 64x128 tiles, grid (bn 16, bm 16, z 32) = 8192 CTAs for latency hiding.
__global__ void __launch_bounds__(256)
gemm_qk(const __half* __restrict__ qf, const __half* __restrict__ wkT,
        __half* __restrict__ qk) {
    __shared__ __align__(16) char sm[24576];   // A 8K + B 16K
    const uint32_t sb = smem_u32(sm);
    const int tid = threadIdx.x, lane = tid & 31, wid = tid >> 5;
    const int wm = wid >> 2, wn = wid & 3;     // warp tile 32x32
    const int bm = blockIdx.y * 64, bn = blockIdx.x * 128, z = blockIdx.z;

#pragma unroll
    for (int it = 0; it < 2; it++) {
        const int idx = it * 256 + tid, r = idx >> 3, c = idx & 7;
        cp16(sb + swzA((uint32_t)(r * 128 + c * 16)),
             qf + (size_t)(bm + r) * 2048 + z * 64 + c * 8);
    }
#pragma unroll
    for (int it = 0; it < 4; it++) {
        const int idx = it * 256 + tid, r = idx >> 3, c = idx & 7;
        cp16(sb + 8192 + swzA((uint32_t)(r * 128 + c * 16)),
             wkT + (size_t)(bn + r) * 2048 + z * 64 + c * 8);
    }
    cp_commit(); cp_wait<0>();
    __syncthreads();

    const int lr = (lane & 7) + ((lane >> 3) & 1) * 8, lc16 = lane >> 4;
    float acc[2][4][4];
#pragma unroll
    for (int i = 0; i < 2; i++)
#pragma unroll
        for (int j = 0; j < 4; j++)
#pragma unroll
            for (int r = 0; r < 4; r++) acc[i][j][r] = 0.f;

#pragma unroll
    for (int kg = 0; kg < 4; kg++) {
        uint32_t a[2][4];
#pragma unroll
        for (int mi = 0; mi < 2; mi++) {
            const uint32_t so =
                swzA((uint32_t)((wm * 32 + mi * 16 + lr) * 128 + kg * 32 + lc16 * 16));
            ldsm4(a[mi][0], a[mi][1], a[mi][2], a[mi][3], sb + so);
        }
#pragma unroll
        for (int nj = 0; nj < 2; nj++) {
            const uint32_t so =
                swzA((uint32_t)((wn * 32 + nj * 16 + lr) * 128 + kg * 32 + lc16 * 16));
            uint32_t h0, h1, h2, h3;
            ldsm4(h0, h1, h2, h3, sb + 8192 + so);
            uint32_t b0[2] = {h0, h2}, b1[2] = {h1, h3};
#pragma unroll
            for (int mi = 0; mi < 2; mi++) {
                mmaf16(acc[mi][nj * 2], a[mi], b0);
                mmaf16(acc[mi][nj * 2 + 1], a[mi], b1);
            }
        }
    }
    const int gr = lane >> 2, gc = (lane & 3) << 1;
#pragma unroll
    for (int mi = 0; mi < 2; mi++)
#pragma unroll
        for (int nn = 0; nn < 4; nn++) {
            const int row = bm + wm * 32 + mi * 16 + gr;
            const int col = bn + wn * 32 + nn * 8 + gc;
            __half2 p0 = __float22half2_rn(make_float2(acc[mi][nn][0], acc[mi][nn][1]));
            __half2 p1 = __float22half2_rn(make_float2(acc[mi][nn][2], acc[mi][nn][3]));
            *(uint32_t*)(qk + ((size_t)row * 32 + z) * 2048 + col) = *(uint32_t*)&p0;
            *(uint32_t*)(qk + ((size_t)(row + 8) * 32 + z) * 2048 + col) = *(uint32_t*)&p1;
        }
}

// ---- batched N=64 fp16 GEMM: att = mixed[z] @ wv_z^T ----
#define N64_A 0
#define N64_B 8192
#define N64_STG 12288
#define N64_SMEM (4 * N64_STG)

__device__ __forceinline__ void n64_load(const __half* A, const __half* B,
                                         int bm, int kc, uint32_t stg, int tid) {
#pragma unroll
    for (int j = 0; j < 2; j++) {
        const int idx = j * 256 + tid, r = idx >> 2, c = idx & 3;
        cp16(stg + N64_A + swz64((uint32_t)(r * 64 + c * 16)),
             A + (size_t)(bm + r) * 2048 + kc + c * 8);
    }
    {
        const int r = tid >> 2, c = tid & 3;
        if (r < 64)
            cp16(stg + N64_B + swz64((uint32_t)(r * 64 + c * 16)),
                 B + (size_t)r * 2048 + kc + c * 8);
    }
}

__global__ void __launch_bounds__(256, 1)
gemm_n64(const __half* __restrict__ A0, const __half* __restrict__ B0,
         __half* __restrict__ Co) {
    extern __shared__ char sm[];
    const uint32_t sb = smem_u32(sm);
    const int tid = threadIdx.x, lane = tid & 31, wid = tid >> 5;
    const int wm = wid >> 1, wn = wid & 1;
    const int bm = blockIdx.x * 128, z = blockIdx.y;
    const __half* A = A0 + (size_t)z * T_ * 2048;
    const __half* B = B0 + (size_t)z * 64 * 2048;

    float acc[2][4][4];
#pragma unroll
    for (int i = 0; i < 2; i++)
#pragma unroll
        for (int j = 0; j < 4; j++)
#pragma unroll
            for (int r = 0; r < 4; r++) acc[i][j][r] = 0.f;

    n64_load(A, B, bm, 0, sb, tid); cp_commit();
    n64_load(A, B, bm, 32, sb + N64_STG, tid); cp_commit();
    n64_load(A, B, bm, 64, sb + 2 * N64_STG, tid); cp_commit();
    const int lr = (lane & 7) + ((lane >> 3) & 1) * 8, lc16 = lane >> 4;

    for (int c = 0; c < 64; c++) {
        cp_wait<2>();
        __syncthreads();
        if (c + 3 < 64)
            n64_load(A, B, bm, (c + 3) * 32, sb + (uint32_t)((c + 3) & 3) * N64_STG, tid);
        cp_commit();
        const uint32_t stg = sb + (uint32_t)(c & 3) * N64_STG;
#pragma unroll
        for (int ks = 0; ks < 2; ks++) {
            uint32_t a[2][4];
#pragma unroll
            for (int mi = 0; mi < 2; mi++) {
                const int r = wm * 32 + mi * 16 + lr;
                const uint32_t so = swz64((uint32_t)(r * 64 + (ks * 2 + lc16) * 16));
                ldsm4(a[mi][0], a[mi][1], a[mi][2], a[mi][3], stg + N64_A + so);
            }
#pragma unroll
            for (int nj = 0; nj < 2; nj++) {
                const int r = wn * 32 + nj * 16 + lr;
                const uint32_t so = swz64((uint32_t)(r * 64 + (ks * 2 + lc16) * 16));
                uint32_t h0, h1, h2, h3;
                ldsm4(h0, h1, h2, h3, stg + N64_B + so);
                uint32_t b0[2] = {h0, h2}, b1[2] = {h1, h3};
#pragma unroll
                for (int mi = 0; mi < 2; mi++) {
                    mmaf16(acc[mi][nj * 2], a[mi], b0);
                    mmaf16(acc[mi][nj * 2 + 1], a[mi], b1);
                }
            }
        }
    }
    const int gr = lane >> 2, gc = (lane & 3) << 1;
#pragma unroll
    for (int mi = 0; mi < 2; mi++)
#pragma unroll
        for (int nn = 0; nn < 4; nn++) {
            const int row = bm + wm * 32 + mi * 16 + gr;
            const int col = wn * 32 + nn * 8 + gc;
            const size_t i0 = (size_t)row * 2048 + z * 64 + col;
            const size_t i1 = i0 + (size_t)8 * 2048;
            __half2 p0 = __float22half2_rn(make_float2(acc[mi][nn][0], acc[mi][nn][1]));
            __half2 p1 = __float22half2_rn(make_float2(acc[mi][nn][2], acc[mi][nn][3]));
            *(uint32_t*)(Co + i0) = *(uint32_t*)&p0;
            *(uint32_t*)(Co + i1) = *(uint32_t*)&p1;
        }
}

// ---- attnmix3: tensor-core scores + softmax + tensor-core mix ----
// scores[32x64] = qk[t](32x2048) @ charwin(64x2048)^T, K streamed in 256-col
// chunks; p<0 char rows zero-filled -> score exactly 0 (reference swa padding).
// mixed[h] = at[h,:64] @ charwin; mix starts at chunks 6,7 (still resident).
// RoPE drops out (q,k share the per-t rotation; v/chars unrotated in reference).
#define MX_QK 0
#define MX_CH 32768
#define MX_SC 98304
#define MX_ATH 106752
#define MX_SMEM 110848
#define SCP 66

__device__ __forceinline__ void ch_load(const __half* chf, int t, int nc,
                                        uint32_t cstg, int tid) {
    const int base = (t - 7) * 8;
#pragma unroll
    for (int it = 0; it < 8; it++) {
        const int idx = it * 256 + tid;
        const int j = idx >> 5, ch = idx & 31;
        const int p = base + j;
        cp16z(cstg + swzB((uint32_t)(j * 512 + ch * 16)),
              chf + (size_t)(p < 0 ? 0 : p) * 2048 + nc * 256 + ch * 8, p >= 0 ? 16 : 0);
    }
}
__device__ __forceinline__ void qk_load(const __half* qk, int t, int nc,
                                        uint32_t qstg, int tid) {
#pragma unroll
    for (int it = 0; it < 4; it++) {
        const int idx = it * 256 + tid;
        const int r = idx >> 5, ch = idx & 31;
        cp16(qstg + swzB((uint32_t)(r * 512 + ch * 16)),
             qk + ((size_t)t * 32 + r) * 2048 + nc * 256 + ch * 8);
    }
}

__global__ void __launch_bounds__(256, 1)
attnmix3(const __half* __restrict__ qk, const __half* __restrict__ chf,
         __half* __restrict__ mx) {
    extern __shared__ char sm[];
    const uint32_t sb = smem_u32(sm);
    float* sc = (float*)(sm + MX_SC);
    const int t = blockIdx.x, tid = threadIdx.x;
    const int lane = tid & 31, wid = tid >> 5;
    const int lr = (lane & 7) + ((lane >> 3) & 1) * 8, lc16 = lane >> 4;

    qk_load(qk, t, 0, sb + MX_QK, tid);
    ch_load(chf, t, 0, sb + MX_CH, tid);
    cp_commit();
    qk_load(qk, t, 1, sb + MX_QK + 16384, tid);
    ch_load(chf, t, 1, sb + MX_CH + 32768, tid);
    cp_commit();

    const int smi = wid >> 2, snj = wid & 3;
    float sa0[4] = {0, 0, 0, 0}, sa1[4] = {0, 0, 0, 0};
    for (int nc = 0; nc < 8; nc++) {
        cp_wait<1>();
        __syncthreads();
        const uint32_t qstg = sb + MX_QK + (uint32_t)(nc & 1) * 16384;
        const uint32_t cstg = sb + MX_CH + (uint32_t)(nc & 1) * 32768;
#pragma unroll
        for (int kg = 0; kg < 16; kg++) {
            uint32_t a[4];
            ldsm4(a[0], a[1], a[2], a[3],
                  qstg + swzB((uint32_t)((smi * 16 + lr) * 512 + kg * 32 + lc16 * 16)));
            uint32_t h0, h1, h2, h3;
            ldsm4(h0, h1, h2, h3,
                  cstg + swzB((uint32_t)((snj * 16 + lr) * 512 + kg * 32 + lc16 * 16)));
            uint32_t b0[2] = {h0, h2}, b1[2] = {h1, h3};
            mmaf16(sa0, a, b0);
            mmaf16(sa1, a, b1);
        }
        __syncthreads();
        if (nc + 2 < 8) {
            qk_load(qk, t, nc + 2, sb + MX_QK + (uint32_t)(nc & 1) * 16384, tid);
            ch_load(chf, t, nc + 2, sb + MX_CH + (uint32_t)(nc & 1) * 32768, tid);
        }
        cp_commit();
    }
    {
        const int gr = lane >> 2, gc = (lane & 3) << 1;
        const int r0 = smi * 16 + gr, c0 = snj * 16 + gc;
        sc[r0 * SCP + c0] = sa0[0] * 0.125f;
        sc[r0 * SCP + c0 + 1] = sa0[1] * 0.125f;
        sc[(r0 + 8) * SCP + c0] = sa0[2] * 0.125f;
        sc[(r0 + 8) * SCP + c0 + 1] = sa0[3] * 0.125f;
        sc[r0 * SCP + c0 + 8] = sa1[0] * 0.125f;
        sc[r0 * SCP + c0 + 9] = sa1[1] * 0.125f;
        sc[(r0 + 8) * SCP + c0 + 8] = sa1[2] * 0.125f;
        sc[(r0 + 8) * SCP + c0 + 9] = sa1[3] * 0.125f;
    }
    __syncthreads();

    {
        const int r = tid >> 3, l8 = tid & 7;
        float vals[8], m = -1e30f;
#pragma unroll
        for (int i = 0; i < 8; i++) { vals[i] = sc[r * SCP + l8 + i * 8]; m = fmaxf(m, vals[i]); }
#pragma unroll
        for (int o = 4; o; o >>= 1) m = fmaxf(m, __shfl_xor_sync(0xffffffffu, m, o));
        float s = 0.f;
#pragma unroll
        for (int i = 0; i < 8; i++) { vals[i] = expf(vals[i] - m); s += vals[i]; }
#pragma unroll
        for (int o = 4; o; o >>= 1) s += __shfl_xor_sync(0xffffffffu, s, o);
        const float inv = 1.f / s;
#pragma unroll
        for (int i = 0; i < 8; i++) {
            const uint32_t o = (uint32_t)(r * 128 + l8 * 2 + i * 16);
            *(__half*)(sm + MX_ATH + swzA(o)) = __float2half_rn(vals[i] * inv);
        }
    }
    __syncthreads();

    uint32_t aH[2][4][4];
#pragma unroll
    for (int mi = 0; mi < 2; mi++)
#pragma unroll
        for (int kg = 0; kg < 4; kg++) {
            const uint32_t o = (uint32_t)((mi * 16 + (lane & 15)) * 128 + kg * 32 + (lane >> 4) * 16);
            ldsm4(aH[mi][kg][0], aH[mi][kg][1], aH[mi][kg][2], aH[mi][kg][3],
                  sb + MX_ATH + swzA(o));
        }

    const int nb = wid * 32;
    for (int i = 0; i < 8; i++) {
        const int nc = (6 + i) & 7;
        if (i >= 2) cp_wait<1>();
        __syncthreads();
        const uint32_t stg = sb + MX_CH + (uint32_t)(nc & 1) * 32768;

        float acc[2][4][4];
#pragma unroll
        for (int ii = 0; ii < 2; ii++)
#pragma unroll
            for (int j = 0; j < 4; j++)
#pragma unroll
                for (int r = 0; r < 4; r++) acc[ii][j][r] = 0.f;

#pragma unroll
        for (int g = 0; g < 2; g++) {
#pragma unroll
            for (int kg = 0; kg < 4; kg++) {
                const uint32_t o = (uint32_t)((kg * 16 + (lane & 15)) * 512 +
                                              nb * 2 + g * 32 + (lane >> 4) * 16);
                uint32_t h0, h1, h2, h3;
                ldsm4t(h0, h1, h2, h3, stg + swzB(o));
                uint32_t b0[2] = {h0, h1}, b1[2] = {h2, h3};
#pragma unroll
                for (int mi = 0; mi < 2; mi++) {
                    mmaf16(acc[mi][g * 2], aH[mi][kg], b0);
                    mmaf16(acc[mi][g * 2 + 1], aH[mi][kg], b1);
                }
            }
        }
        const int gr = lane >> 2, gc = (lane & 3) << 1;
#pragma unroll
        for (int mi = 0; mi < 2; mi++)
#pragma unroll
            for (int nj = 0; nj < 4; nj++) {
                const int h = mi * 16 + gr;
                const int col = nc * 256 + nb + nj * 8 + gc;
                const size_t i0 = ((size_t)h * T_ + t) * 2048 + col;
                const size_t i1 = ((size_t)(h + 8) * T_ + t) * 2048 + col;
                __half2 p0 = __float22half2_rn(make_float2(acc[mi][nj][0], acc[mi][nj][1]));
                __half2 p1 = __float22half2_rn(make_float2(acc[mi][nj][2], acc[mi][nj][3]));
                *(uint32_t*)(mx + i0) = *(uint32_t*)&p0;
                *(uint32_t*)(mx + i1) = *(uint32_t*)&p1;
            }
        __syncthreads();
        if (i + 2 < 8) ch_load(chf, t, (6 + i + 2) & 7, stg, tid);
        cp_commit();
    }
}

extern "C" void kernel_launch(void* const* d_in, const int* in_sizes, int n_in,
                              void* d_out, int out_size) {
    const float* x = (const float*)d_in[0];
    const float* chars = (const float*)d_in[1];
    const float* wq = (const float*)d_in[2];
    const float* wk = (const float*)d_in[3];
    const float* wv = (const float*)d_in[4];
    const float* wo = (const float*)d_in[5];
    float* out = (float*)d_out;

    __half *qf, *xf, *chf, *wqf, *wktf, *wvf, *wof, *qkf, *mxf, *attf;
    cudaGetSymbolAddress((void**)&qf, g_qf);     cudaGetSymbolAddress((void**)&xf, g_xf);
    cudaGetSymbolAddress((void**)&chf, g_chf);   cudaGetSymbolAddress((void**)&wqf, g_wqf);
    cudaGetSymbolAddress((void**)&wktf, g_wktf); cudaGetSymbolAddress((void**)&wvf, g_wvf);
    cudaGetSymbolAddress((void**)&wof, g_wof);   cudaGetSymbolAddress((void**)&qkf, g_qkf);
    cudaGetSymbolAddress((void**)&mxf, g_mxf);   cudaGetSymbolAddress((void**)&attf, g_attf);

    cudaFuncSetAttribute(gemm_f16s<0>, cudaFuncAttributeMaxDynamicSharedMemorySize, S_SMEM);
    cudaFuncSetAttribute(gemm_f16s<1>, cudaFuncAttributeMaxDynamicSharedMemorySize, S_SMEM);
    cudaFuncSetAttribute(gemm_n64, cudaFuncAttributeMaxDynamicSharedMemorySize, N64_SMEM);
    cudaFuncSetAttribute(attnmix3, cudaFuncAttributeMaxDynamicSharedMemorySize, MX_SMEM);

    // single prep launch: 5 fp32->fp16 converts + wk transpose
    cvt_multi<<<dim3(2048, 6), 256>>>(
        (const float4*)x,     (uint2*)xf,  T_ * DIM_ / 4,
        (const float4*)chars, (uint2*)chf, T_ * 8 * DIM_ / 4,
        (const float4*)wq,    (uint2*)wqf, DIM_ * DIM_ / 4,
        (const float4*)wv,    (uint2*)wvf, DIM_ * DIM_ / 4,
        (const float4*)wo,    (uint2*)wof, DIM_ * DIM_ / 4,
        wk, wktf);

    gemm_f16s<1><<<dim3(16, 8), 256, S_SMEM>>>(xf, wqf, nullptr, qf);   // q (fp16)
    gemm_qk<<<dim3(16, 16, 32), 256>>>(qf, wktf, qkf);                  // qk (64x128)
    attnmix3<<<T_, 256, MX_SMEM>>>(qkf, chf, mxf);                      // scores+softmax+mix
    gemm_n64<<<dim3(8, 32), 256, N64_SMEM>>>(mxf, wvf, attf);           // v proj
    gemm_f16s<0><<<dim3(16, 8), 256, S_SMEM>>>(attf, wof, out, nullptr); // o proj
}